// round 1
// baseline (speedup 1.0000x reference)
#include <cuda_runtime.h>
#include <cstdint>

// Problem constants
#define B_  4
#define S_  2048
#define D_  1024
#define H_  16
#define DH_ 64
#define M_  (B_*S_)   // 8192 tokens

// Scratch (device globals: allocation-free per harness rules)
__device__ float g_q[(size_t)B_*H_*S_*DH_];    // [B,H,S,Dh]
__device__ float g_k[(size_t)B_*H_*S_*DH_];
__device__ float g_v[(size_t)B_*H_*S_*DH_];
__device__ float g_ctx[(size_t)M_*D_];         // [B,S,D]

// ---------------------------------------------------------------------------
// Packed f32x2 helpers (Blackwell FFMA2 — ptxas won't auto-fuse, must be PTX)
// ---------------------------------------------------------------------------
__device__ __forceinline__ unsigned long long pack2(float x, float y) {
    unsigned long long r;
    asm("mov.b64 %0, {%1, %2};" : "=l"(r) : "f"(x), "f"(y));
    return r;
}
__device__ __forceinline__ void fma2(unsigned long long& d,
                                     unsigned long long a,
                                     unsigned long long b) {
    asm("fma.rn.f32x2 %0, %1, %2, %0;" : "+l"(d) : "l"(a), "l"(b));
}

// ---------------------------------------------------------------------------
// GEMM: out = A[M,K=1024] @ W[K=1024,N=1024] + bias
// mode 0: out row-major [M,N]
// mode 1: out split-head layout q[b,h,s,d] (= Y[b,s,h*64+d])
// Block 64x64, K-tile 16, 256 threads, thread tile 4x4, FFMA2 inner loop.
// ---------------------------------------------------------------------------
__global__ __launch_bounds__(256) void gemm_bias_kernel(
    const float* __restrict__ A, const float* __restrict__ W,
    const float* __restrict__ bias, float* __restrict__ out, int mode)
{
    __shared__ float As[16][68];   // stride 68 keeps float4 alignment (272B rows)
    __shared__ float Bs[16][68];

    const int tid = threadIdx.x;
    const int tx = tid & 15, ty = tid >> 4;
    const int bm = blockIdx.y * 64, bn = blockIdx.x * 64;
    const int arow = tid >> 2, ac4 = tid & 3;     // A tile loader mapping
    const int wrow = tid >> 4, wc4 = tid & 15;    // W tile loader mapping

    unsigned long long acc[4][2];
#pragma unroll
    for (int i = 0; i < 4; i++) { acc[i][0] = 0ull; acc[i][1] = 0ull; }

    for (int k0 = 0; k0 < D_; k0 += 16) {
        float4 a4 = *(const float4*)(A + (size_t)(bm + arow) * D_ + k0 + ac4 * 4);
        As[ac4*4+0][arow] = a4.x; As[ac4*4+1][arow] = a4.y;
        As[ac4*4+2][arow] = a4.z; As[ac4*4+3][arow] = a4.w;
        float4 w4 = *(const float4*)(W + (size_t)(k0 + wrow) * D_ + bn + wc4 * 4);
        *(float4*)&Bs[wrow][wc4*4] = w4;
        __syncthreads();

#pragma unroll
        for (int kk = 0; kk < 16; kk++) {
            float4 av = *(const float4*)&As[kk][ty*4];
            unsigned long long b0 = *(const unsigned long long*)&Bs[kk][tx*4];
            unsigned long long b1 = *(const unsigned long long*)&Bs[kk][tx*4 + 2];
            unsigned long long a0 = pack2(av.x, av.x);
            unsigned long long a1 = pack2(av.y, av.y);
            unsigned long long a2 = pack2(av.z, av.z);
            unsigned long long a3 = pack2(av.w, av.w);
            fma2(acc[0][0], a0, b0); fma2(acc[0][1], a0, b1);
            fma2(acc[1][0], a1, b0); fma2(acc[1][1], a1, b1);
            fma2(acc[2][0], a2, b0); fma2(acc[2][1], a2, b1);
            fma2(acc[3][0], a3, b0); fma2(acc[3][1], a3, b1);
        }
        __syncthreads();
    }

#pragma unroll
    for (int i = 0; i < 4; i++) {
        const int row = bm + ty*4 + i;
#pragma unroll
        for (int j2 = 0; j2 < 2; j2++) {
            float lo, hi;
            asm("mov.b64 {%0, %1}, %2;" : "=f"(lo), "=f"(hi) : "l"(acc[i][j2]));
            const int c0 = bn + tx*4 + j2*2;   // even column
            const float y0 = lo + bias[c0];
            const float y1 = hi + bias[c0 + 1];
            if (mode == 0) {
                out[(size_t)row * D_ + c0]     = y0;
                out[(size_t)row * D_ + c0 + 1] = y1;
            } else {
                const int b = row >> 11, s = row & 2047;   // S_=2048
                const int h = c0 >> 6,  d = c0 & 63;       // d<=62, pair same head
                const size_t o = (((size_t)(b * H_ + h)) * S_ + s) * DH_ + d;
                out[o] = y0; out[o + 1] = y1;
            }
        }
    }
}

// ---------------------------------------------------------------------------
// Flash attention, fp32. One block = one (b,h) x 64-row Q tile.
// 256 threads: thread t owns q-row r=t/4 and a 16-wide column/dim slice g=t%4.
// Score scale is 1/Dh^2 = 1/4096 (faithful to reference).
// ---------------------------------------------------------------------------
__global__ __launch_bounds__(256, 2) void flash_attn_kernel(
    const float* __restrict__ gq, const float* __restrict__ gk,
    const float* __restrict__ gv, const int* __restrict__ mask,
    float* __restrict__ ctx)
{
    extern __shared__ float smbuf[];
    float* Qs = smbuf;              // 64*68; reused as Ss after Q -> regs
    float* Ks = smbuf + 64*68;
    float* Vs = smbuf + 2*64*68;
    int*   msk = (int*)(smbuf + 3*64*68);
    float* Ss = Qs;

    const int tid = threadIdx.x;
    const int r = tid >> 2, g = tid & 3;
    const int bh = blockIdx.y;
    const int b = bh >> 4, h = bh & 15;
    const int it = blockIdx.x;
    const int qbase = it * 64;

    // Load Q tile into smem (coalesced), then thread's row into registers.
    const float* qp = gq + ((size_t)bh * S_ + qbase) * DH_;
    for (int idx = tid; idx < 64*64; idx += 256)
        Qs[(idx >> 6) * 68 + (idx & 63)] = qp[idx];
    __syncthreads();
    float4 qr[16];
#pragma unroll
    for (int d4 = 0; d4 < 16; d4++) qr[d4] = *(const float4*)&Qs[r*68 + d4*4];

    float m = -1e30f, l = 0.f;
    float accv[16];
#pragma unroll
    for (int i = 0; i < 16; i++) accv[i] = 0.f;

    for (int jt = 0; jt <= it; jt++) {
        __syncthreads();   // prior-iter Ss/Vs reads done; qr copies done (iter 0)

        const float* kp = gk + ((size_t)bh * S_ + jt * 64) * DH_;
        const float* vp = gv + ((size_t)bh * S_ + jt * 64) * DH_;
        for (int idx = tid; idx < 64*64; idx += 256) {
            const int row = idx >> 6, d = idx & 63;
            Ks[row*68 + d] = kp[idx];
            Vs[row*68 + d] = vp[idx];
        }
        if (tid < 64) msk[tid] = mask[b * S_ + jt * 64 + tid];
        __syncthreads();

        // ---- scores: S[r, g*16..g*16+15] ----
        float sv[16];
        float tmax = -1e30f;
#pragma unroll
        for (int c = 0; c < 16; c++) {
            const int col = g*16 + c;
            const float* kc = Ks + col*68;
            float s = 0.f;
#pragma unroll
            for (int d4 = 0; d4 < 16; d4++) {
                const float4 k4 = *(const float4*)(kc + d4*4);
                s += qr[d4].x * k4.x + qr[d4].y * k4.y
                   + qr[d4].z * k4.z + qr[d4].w * k4.w;
            }
            s *= (1.0f / 4096.0f);     // 1/Dh^2 per reference
            const bool valid = (msk[col] != 0) && (jt*64 + col <= qbase + r);
            s = valid ? s : -1e30f;
            sv[c] = s;
            tmax = fmaxf(tmax, s);
        }
        // reduce across the 4-thread row group (adjacent lanes)
        tmax = fmaxf(tmax, __shfl_xor_sync(0xffffffffu, tmax, 1));
        tmax = fmaxf(tmax, __shfl_xor_sync(0xffffffffu, tmax, 2));
        const float mnew  = fmaxf(m, tmax);
        const float alpha = __expf(m - mnew);

        float tsum = 0.f;
#pragma unroll
        for (int c = 0; c < 16; c++) {
            const float p = (sv[c] > -1e29f) ? __expf(sv[c] - mnew) : 0.f;
            Ss[r*68 + g*16 + c] = p;
            tsum += p;
        }
        tsum += __shfl_xor_sync(0xffffffffu, tsum, 1);
        tsum += __shfl_xor_sync(0xffffffffu, tsum, 2);
        l = l * alpha + tsum;
#pragma unroll
        for (int i = 0; i < 16; i++) accv[i] *= alpha;
        m = mnew;
        __syncthreads();  // Ss visible to all row-group threads

        // ---- O[r, g*16..] += P[r,:] @ V[:, g*16..] ----
        const int dd = g * 16;
#pragma unroll 4
        for (int k = 0; k < 64; k++) {
            const float p = Ss[r*68 + k];
            const float4* vr = (const float4*)(Vs + k*68 + dd);
            const float4 v0 = vr[0], v1 = vr[1], v2 = vr[2], v3 = vr[3];
            accv[0]  += p * v0.x; accv[1]  += p * v0.y; accv[2]  += p * v0.z; accv[3]  += p * v0.w;
            accv[4]  += p * v1.x; accv[5]  += p * v1.y; accv[6]  += p * v1.z; accv[7]  += p * v1.w;
            accv[8]  += p * v2.x; accv[9]  += p * v2.y; accv[10] += p * v2.z; accv[11] += p * v2.w;
            accv[12] += p * v3.x; accv[13] += p * v3.y; accv[14] += p * v3.z; accv[15] += p * v3.w;
        }
    }

    const float invl = 1.0f / fmaxf(l, 1e-37f);
    float* op = ctx + ((size_t)(b * S_) + qbase + r) * D_ + h * DH_ + g * 16;
    float4 o0 = make_float4(accv[0]*invl,  accv[1]*invl,  accv[2]*invl,  accv[3]*invl);
    float4 o1 = make_float4(accv[4]*invl,  accv[5]*invl,  accv[6]*invl,  accv[7]*invl);
    float4 o2 = make_float4(accv[8]*invl,  accv[9]*invl,  accv[10]*invl, accv[11]*invl);
    float4 o3 = make_float4(accv[12]*invl, accv[13]*invl, accv[14]*invl, accv[15]*invl);
    *(float4*)(op + 0)  = o0;
    *(float4*)(op + 4)  = o1;
    *(float4*)(op + 8)  = o2;
    *(float4*)(op + 12) = o3;
}

// ---------------------------------------------------------------------------
extern "C" void kernel_launch(void* const* d_in, const int* in_sizes, int n_in,
                              void* d_out, int out_size)
{
    const float* query = (const float*)d_in[0];
    const float* key   = (const float*)d_in[1];
    const float* value = (const float*)d_in[2];
    const int*   mask  = (const int*)  d_in[3];
    const float* Wq = (const float*)d_in[4];  const float* bq = (const float*)d_in[5];
    const float* Wk = (const float*)d_in[6];  const float* bk = (const float*)d_in[7];
    const float* Wv = (const float*)d_in[8];  const float* bv = (const float*)d_in[9];
    const float* Wo = (const float*)d_in[10]; const float* bo = (const float*)d_in[11];

    float *q, *k, *v, *ctx;
    cudaGetSymbolAddress((void**)&q,   g_q);
    cudaGetSymbolAddress((void**)&k,   g_k);
    cudaGetSymbolAddress((void**)&v,   g_v);
    cudaGetSymbolAddress((void**)&ctx, g_ctx);

    dim3 gg(D_ / 64, M_ / 64);   // (16, 128)
    gemm_bias_kernel<<<gg, 256>>>(query, Wq, bq, q, 1);
    gemm_bias_kernel<<<gg, 256>>>(key,   Wk, bk, k, 1);
    gemm_bias_kernel<<<gg, 256>>>(value, Wv, bv, v, 1);

    const int shmem = 3 * 64 * 68 * (int)sizeof(float) + 64 * (int)sizeof(int);
    cudaFuncSetAttribute(flash_attn_kernel,
                         cudaFuncAttributeMaxDynamicSharedMemorySize, shmem);
    flash_attn_kernel<<<dim3(S_ / 64, B_ * H_), 256, shmem>>>(q, k, v, mask, ctx);

    gemm_bias_kernel<<<gg, 256>>>(ctx, Wo, bo, (float*)d_out, 0);
}

// round 2
// speedup vs baseline: 7.4637x; 7.4637x over previous
#include <cuda_runtime.h>
#include <cstdint>

#define B_  4
#define S_  2048
#define D_  1024
#define H_  16
#define DH_ 64
#define M_  (B_*S_)   // 8192 tokens

// Scratch (device globals: allocation-free per harness rules)
__device__ float g_q[(size_t)M_*D_];    // [B,H,S,Dh]
__device__ float g_k[(size_t)M_*D_];
__device__ float g_v[(size_t)M_*D_];
__device__ float g_ctx[(size_t)M_*D_];  // [B,S,D]

// ---------------------------------------------------------------------------
// tf32 helpers
// ---------------------------------------------------------------------------
__device__ __forceinline__ unsigned f2tf(float x) {
    unsigned r; asm("cvt.rna.tf32.f32 %0, %1;" : "=r"(r) : "f"(x)); return r;
}
// D += A(16x8) * B(8x8), tf32 inputs, f32 accum
__device__ __forceinline__ void mma8(float* c, const unsigned* a, const unsigned* b) {
    asm volatile("mma.sync.aligned.m16n8k8.row.col.f32.tf32.tf32.f32 "
        "{%0,%1,%2,%3}, {%4,%5,%6,%7}, {%8,%9}, {%0,%1,%2,%3};"
        : "+f"(c[0]), "+f"(c[1]), "+f"(c[2]), "+f"(c[3])
        : "r"(a[0]), "r"(a[1]), "r"(a[2]), "r"(a[3]), "r"(b[0]), "r"(b[1]));
}

// ---------------------------------------------------------------------------
// GEMM: out = A[M,1024] @ W[1024,1024] + bias  (tf32 tensor cores)
// Block tile 128x128, K-tile 32, 256 threads = 8 warps (2x4), warp tile 64x32.
// mode 0: out row-major [M,1024];  mode 1: split-head layout [b,h,s,d]
// ---------------------------------------------------------------------------
__global__ __launch_bounds__(256) void gemm_tf32(
    const float* __restrict__ A, const float* __restrict__ W,
    const float* __restrict__ bias, float* __restrict__ out, int mode)
{
    __shared__ unsigned As[128][36];   // [m][k], pad 4: frag banks 4g+t unique
    __shared__ unsigned Bs[32][136];   // [k][n], pad 8: frag banks 8t+g unique

    const int tid  = threadIdx.x;
    const int lane = tid & 31, warp = tid >> 5;
    const int wm = (warp >> 2) * 64;        // 0 | 64
    const int wn = (warp & 3) * 32;         // 0,32,64,96
    const int g = lane >> 2, t = lane & 3;
    const int bm = blockIdx.y * 128, bn = blockIdx.x * 128;

    float acc[4][4][4];
#pragma unroll
    for (int mt = 0; mt < 4; mt++)
#pragma unroll
        for (int nt = 0; nt < 4; nt++)
#pragma unroll
            for (int i = 0; i < 4; i++) acc[mt][nt][i] = 0.f;

    for (int k0 = 0; k0 < D_; k0 += 32) {
#pragma unroll
        for (int i = 0; i < 4; i++) {
            const int idx = tid + i * 256;
            const int ra = idx >> 3, ca = idx & 7;        // A: 128 rows x 8 float4
            float4 a4 = *(const float4*)(A + (size_t)(bm + ra) * D_ + k0 + ca * 4);
            As[ra][ca*4+0] = f2tf(a4.x); As[ra][ca*4+1] = f2tf(a4.y);
            As[ra][ca*4+2] = f2tf(a4.z); As[ra][ca*4+3] = f2tf(a4.w);
            const int rb = idx >> 5, cb = idx & 31;       // B: 32 rows x 32 float4
            float4 w4 = *(const float4*)(W + (size_t)(k0 + rb) * D_ + bn + cb * 4);
            Bs[rb][cb*4+0] = f2tf(w4.x); Bs[rb][cb*4+1] = f2tf(w4.y);
            Bs[rb][cb*4+2] = f2tf(w4.z); Bs[rb][cb*4+3] = f2tf(w4.w);
        }
        __syncthreads();

#pragma unroll
        for (int ks = 0; ks < 4; ks++) {
            unsigned af[4][4], bf[4][2];
#pragma unroll
            for (int mt = 0; mt < 4; mt++) {
                const int r0 = wm + mt * 16 + g;
                af[mt][0] = As[r0    ][ks*8 + t];
                af[mt][1] = As[r0 + 8][ks*8 + t];
                af[mt][2] = As[r0    ][ks*8 + t + 4];
                af[mt][3] = As[r0 + 8][ks*8 + t + 4];
            }
#pragma unroll
            for (int nt = 0; nt < 4; nt++) {
                bf[nt][0] = Bs[ks*8 + t    ][wn + nt*8 + g];
                bf[nt][1] = Bs[ks*8 + t + 4][wn + nt*8 + g];
            }
#pragma unroll
            for (int mt = 0; mt < 4; mt++)
#pragma unroll
                for (int nt = 0; nt < 4; nt++)
                    mma8(acc[mt][nt], af[mt], bf[nt]);
        }
        __syncthreads();
    }

    // Epilogue: C frag (c0,c1)->(row g, cols 2t,2t+1), (c2,c3)->(row g+8)
#pragma unroll
    for (int mt = 0; mt < 4; mt++) {
#pragma unroll
        for (int nt = 0; nt < 4; nt++) {
            const int row0 = bm + wm + mt * 16 + g;
            const int col  = bn + wn + nt * 8 + t * 2;
            const float b0 = bias[col], b1 = bias[col + 1];
            float2 y0 = make_float2(acc[mt][nt][0] + b0, acc[mt][nt][1] + b1);
            float2 y1 = make_float2(acc[mt][nt][2] + b0, acc[mt][nt][3] + b1);
            if (mode == 0) {
                *(float2*)(out + (size_t)row0 * D_ + col)       = y0;
                *(float2*)(out + (size_t)(row0 + 8) * D_ + col) = y1;
            } else {
                const int h = col >> 6, d = col & 63;
                const int b_i0 = row0 >> 11, s0 = row0 & 2047;
                const int b_i1 = (row0 + 8) >> 11, s1 = (row0 + 8) & 2047;
                *(float2*)(out + (((size_t)(b_i0 * H_ + h)) * S_ + s0) * DH_ + d) = y0;
                *(float2*)(out + (((size_t)(b_i1 * H_ + h)) * S_ + s1) * DH_ + d) = y1;
            }
        }
    }
}

// ---------------------------------------------------------------------------
// Flash attention, tf32 tensor cores. Block = (b,h) x 64 q-rows, 4 warps.
// Warp w owns q-rows [w*16, w*16+16). Score scale 1/Dh^2 = 1/4096 (faithful).
// ---------------------------------------------------------------------------
__global__ __launch_bounds__(128) void attn_tf32(
    const float* __restrict__ gq, const float* __restrict__ gk,
    const float* __restrict__ gv, const int* __restrict__ mask,
    float* __restrict__ ctx)
{
    extern __shared__ unsigned sm[];
    unsigned* Qs = sm;                 // 64x68 (Q, reused as P per-warp-private)
    unsigned* Ks = sm + 64 * 68;       // 64x68  (banks: 4g+t unique)
    unsigned* Vs = sm + 2 * 64 * 68;   // 64x72  (banks: 8t+g unique)
    int* msk = (int*)(sm + 2 * 64 * 68 + 64 * 72);

    const int tid  = threadIdx.x;
    const int lane = tid & 31, warp = tid >> 5;
    const int g = lane >> 2, t = lane & 3;
    const int bh = blockIdx.y, b = bh >> 4, h = bh & 15;
    const int it = blockIdx.x, qbase = it * 64;

    // Load Q tile (coalesced, cvt to tf32)
    const float* qp = gq + ((size_t)bh * S_ + qbase) * DH_;
    for (int i = 0; i < 8; i++) {
        const int idx = tid + i * 128;
        const int row = idx >> 4, c4 = idx & 15;
        float4 q4 = *(const float4*)(qp + row * DH_ + c4 * 4);
        Qs[row*68 + c4*4+0] = f2tf(q4.x); Qs[row*68 + c4*4+1] = f2tf(q4.y);
        Qs[row*68 + c4*4+2] = f2tf(q4.z); Qs[row*68 + c4*4+3] = f2tf(q4.w);
    }
    __syncthreads();

    // Q fragments (held for whole kernel); warp reads only its own 16 rows.
    unsigned qf[8][4];
#pragma unroll
    for (int ks = 0; ks < 8; ks++) {
        const int r0 = warp * 16 + g;
        qf[ks][0] = Qs[(r0    )*68 + ks*8 + t];
        qf[ks][1] = Qs[(r0 + 8)*68 + ks*8 + t];
        qf[ks][2] = Qs[(r0    )*68 + ks*8 + t + 4];
        qf[ks][3] = Qs[(r0 + 8)*68 + ks*8 + t + 4];
    }

    float m0 = -1e30f, m1 = -1e30f, l0 = 0.f, l1 = 0.f;
    float o[8][4];
#pragma unroll
    for (int nt = 0; nt < 8; nt++)
#pragma unroll
        for (int i = 0; i < 4; i++) o[nt][i] = 0.f;

    const int row0g = qbase + warp * 16 + g;   // global q row for c0,c1
    const int row1g = row0g + 8;               // for c2,c3

    for (int jt = 0; jt <= it; jt++) {
        __syncthreads();   // prior-iter K/V frag reads complete
        const float* kp = gk + ((size_t)bh * S_ + jt * 64) * DH_;
        const float* vp = gv + ((size_t)bh * S_ + jt * 64) * DH_;
        for (int i = 0; i < 8; i++) {
            const int idx = tid + i * 128;
            const int row = idx >> 4, c4 = idx & 15;
            float4 k4 = *(const float4*)(kp + row * DH_ + c4 * 4);
            Ks[row*68 + c4*4+0] = f2tf(k4.x); Ks[row*68 + c4*4+1] = f2tf(k4.y);
            Ks[row*68 + c4*4+2] = f2tf(k4.z); Ks[row*68 + c4*4+3] = f2tf(k4.w);
            float4 v4 = *(const float4*)(vp + row * DH_ + c4 * 4);
            Vs[row*72 + c4*4+0] = f2tf(v4.x); Vs[row*72 + c4*4+1] = f2tf(v4.y);
            Vs[row*72 + c4*4+2] = f2tf(v4.z); Vs[row*72 + c4*4+3] = f2tf(v4.w);
        }
        if (tid < 64) msk[tid] = mask[b * S_ + jt * 64 + tid];
        __syncthreads();

        // ---- S = Q @ K^T ----
        float s[8][4];
#pragma unroll
        for (int nt = 0; nt < 8; nt++)
#pragma unroll
            for (int i = 0; i < 4; i++) s[nt][i] = 0.f;
#pragma unroll
        for (int ks = 0; ks < 8; ks++) {
#pragma unroll
            for (int nt = 0; nt < 8; nt++) {
                unsigned bf[2];
                bf[0] = Ks[(nt*8 + g)*68 + ks*8 + t];
                bf[1] = Ks[(nt*8 + g)*68 + ks*8 + t + 4];
                mma8(s[nt], qf[ks], bf);
            }
        }

        // ---- masking + online softmax ----
        const float inv = 1.0f / 4096.0f;
        float tmax0 = -1e30f, tmax1 = -1e30f;
#pragma unroll
        for (int nt = 0; nt < 8; nt++) {
            const int colb = nt*8 + t*2;
            const int key  = jt*64 + colb;
            const bool mk0 = msk[colb] != 0, mk1 = msk[colb+1] != 0;
            s[nt][0] = (mk0 && key     <= row0g) ? s[nt][0]*inv : -1e30f;
            s[nt][1] = (mk1 && key + 1 <= row0g) ? s[nt][1]*inv : -1e30f;
            s[nt][2] = (mk0 && key     <= row1g) ? s[nt][2]*inv : -1e30f;
            s[nt][3] = (mk1 && key + 1 <= row1g) ? s[nt][3]*inv : -1e30f;
            tmax0 = fmaxf(tmax0, fmaxf(s[nt][0], s[nt][1]));
            tmax1 = fmaxf(tmax1, fmaxf(s[nt][2], s[nt][3]));
        }
        tmax0 = fmaxf(tmax0, __shfl_xor_sync(0xffffffffu, tmax0, 1));
        tmax0 = fmaxf(tmax0, __shfl_xor_sync(0xffffffffu, tmax0, 2));
        tmax1 = fmaxf(tmax1, __shfl_xor_sync(0xffffffffu, tmax1, 1));
        tmax1 = fmaxf(tmax1, __shfl_xor_sync(0xffffffffu, tmax1, 2));

        const float mn0 = fmaxf(m0, tmax0), mn1 = fmaxf(m1, tmax1);
        const float a0 = __expf(m0 - mn0), a1 = __expf(m1 - mn1);

        unsigned* Ps = Qs;
        float sum0 = 0.f, sum1 = 0.f;
        const int pr0 = warp * 16 + g;
#pragma unroll
        for (int nt = 0; nt < 8; nt++) {
            const int colb = nt*8 + t*2;
            unsigned pb[4];
            float pv;
            pv = (s[nt][0] > -1e29f) ? __expf(s[nt][0] - mn0) : 0.f;
            pb[0] = f2tf(pv); sum0 += __uint_as_float(pb[0]);
            pv = (s[nt][1] > -1e29f) ? __expf(s[nt][1] - mn0) : 0.f;
            pb[1] = f2tf(pv); sum0 += __uint_as_float(pb[1]);
            pv = (s[nt][2] > -1e29f) ? __expf(s[nt][2] - mn1) : 0.f;
            pb[2] = f2tf(pv); sum1 += __uint_as_float(pb[2]);
            pv = (s[nt][3] > -1e29f) ? __expf(s[nt][3] - mn1) : 0.f;
            pb[3] = f2tf(pv); sum1 += __uint_as_float(pb[3]);
            *(uint2*)&Ps[(pr0    )*68 + colb] = make_uint2(pb[0], pb[1]);
            *(uint2*)&Ps[(pr0 + 8)*68 + colb] = make_uint2(pb[2], pb[3]);
        }
        sum0 += __shfl_xor_sync(0xffffffffu, sum0, 1);
        sum0 += __shfl_xor_sync(0xffffffffu, sum0, 2);
        sum1 += __shfl_xor_sync(0xffffffffu, sum1, 1);
        sum1 += __shfl_xor_sync(0xffffffffu, sum1, 2);
        l0 = l0 * a0 + sum0;  l1 = l1 * a1 + sum1;
        m0 = mn0;  m1 = mn1;
#pragma unroll
        for (int nt = 0; nt < 8; nt++) {
            o[nt][0] *= a0; o[nt][1] *= a0;
            o[nt][2] *= a1; o[nt][3] *= a1;
        }
        __syncwarp();   // P stores visible within warp (P region is warp-private)

        // ---- O += P @ V ----
#pragma unroll
        for (int ks = 0; ks < 8; ks++) {
            unsigned pf[4];
            pf[0] = Ps[(pr0    )*68 + ks*8 + t];
            pf[1] = Ps[(pr0 + 8)*68 + ks*8 + t];
            pf[2] = Ps[(pr0    )*68 + ks*8 + t + 4];
            pf[3] = Ps[(pr0 + 8)*68 + ks*8 + t + 4];
#pragma unroll
            for (int nt = 0; nt < 8; nt++) {
                unsigned vb[2];
                vb[0] = Vs[(ks*8 + t    )*72 + nt*8 + g];
                vb[1] = Vs[(ks*8 + t + 4)*72 + nt*8 + g];
                mma8(o[nt], pf, vb);
            }
        }
        __syncwarp();
    }

    // ---- epilogue: normalize + write ctx[b, s, h*64 + d] ----
    const float il0 = 1.0f / fmaxf(l0, 1e-30f);
    const float il1 = 1.0f / fmaxf(l1, 1e-30f);
    float* op0 = ctx + ((size_t)(b * S_) + row0g) * D_ + h * DH_;
    float* op1 = op0 + 8 * D_;
#pragma unroll
    for (int nt = 0; nt < 8; nt++) {
        const int col = nt*8 + t*2;
        *(float2*)(op0 + col) = make_float2(o[nt][0] * il0, o[nt][1] * il0);
        *(float2*)(op1 + col) = make_float2(o[nt][2] * il1, o[nt][3] * il1);
    }
}

// ---------------------------------------------------------------------------
extern "C" void kernel_launch(void* const* d_in, const int* in_sizes, int n_in,
                              void* d_out, int out_size)
{
    const float* query = (const float*)d_in[0];
    const float* key   = (const float*)d_in[1];
    const float* value = (const float*)d_in[2];
    const int*   mask  = (const int*)  d_in[3];
    const float* Wq = (const float*)d_in[4];  const float* bq = (const float*)d_in[5];
    const float* Wk = (const float*)d_in[6];  const float* bk = (const float*)d_in[7];
    const float* Wv = (const float*)d_in[8];  const float* bv = (const float*)d_in[9];
    const float* Wo = (const float*)d_in[10]; const float* bo = (const float*)d_in[11];

    float *q, *k, *v, *ctx;
    cudaGetSymbolAddress((void**)&q,   g_q);
    cudaGetSymbolAddress((void**)&k,   g_k);
    cudaGetSymbolAddress((void**)&v,   g_v);
    cudaGetSymbolAddress((void**)&ctx, g_ctx);

    dim3 gg(D_ / 128, M_ / 128);   // (8, 64)
    gemm_tf32<<<gg, 256>>>(query, Wq, bq, q, 1);
    gemm_tf32<<<gg, 256>>>(key,   Wk, bk, k, 1);
    gemm_tf32<<<gg, 256>>>(value, Wv, bv, v, 1);

    const int shmem = (2 * 64 * 68 + 64 * 72) * (int)sizeof(unsigned)
                    + 64 * (int)sizeof(int);
    cudaFuncSetAttribute(attn_tf32,
                         cudaFuncAttributeMaxDynamicSharedMemorySize, shmem);
    attn_tf32<<<dim3(S_ / 64, B_ * H_), 128, shmem>>>(q, k, v, mask, ctx);

    gemm_tf32<<<gg, 256>>>(ctx, Wo, bo, (float*)d_out, 0);
}